// round 13
// baseline (speedup 1.0000x reference)
#include <cuda_runtime.h>

// ---------------- scratch (no allocations allowed) ----------------
__device__ __align__(16) float g_qkv[4 * 16 * 1024 * 8];   // [B,H,S,8] GAMMA-scaled, 2MB
__device__ __align__(16) float g_attn[4 * 1024 * 16 * 8];  // [B,S,H,8]  2MB
__device__ __align__(16) float g_wt[128 * 128];            // W transposed [e][j]

// GAMMA^2 = log2(e)/sqrt(8); dot of GAMMA-scaled vectors = score*log2(e) directly.
#define GAMMA     0.7142163217f
#define INV_GAMMA 1.4001353259f

// ---------------- f32x2 packed helpers (Blackwell dual-FMA pipe) ----------------
typedef unsigned long long u64;

__device__ __forceinline__ u64 f2mul(u64 a, u64 b) {
    u64 d; asm("mul.rn.f32x2 %0, %1, %2;" : "=l"(d) : "l"(a), "l"(b)); return d;
}
__device__ __forceinline__ u64 f2add(u64 a, u64 b) {
    u64 d; asm("add.rn.f32x2 %0, %1, %2;" : "=l"(d) : "l"(a), "l"(b)); return d;
}
__device__ __forceinline__ u64 f2fma(u64 a, u64 b, u64 c) {
    u64 d; asm("fma.rn.f32x2 %0, %1, %2, %3;" : "=l"(d) : "l"(a), "l"(b), "l"(c)); return d;
}
__device__ __forceinline__ u64 f2pack(float lo, float hi) {
    u64 d; asm("mov.b64 %0, {%1, %2};" : "=l"(d) : "f"(lo), "f"(hi)); return d;
}
__device__ __forceinline__ void f2unpack(u64 v, float& lo, float& hi) {
    asm("mov.b64 {%0, %1}, %2;" : "=f"(lo), "=f"(hi) : "l"(v));
}
__device__ __forceinline__ u64 f2bcast(float x) { return f2pack(x, x); }

// MUFU exp2 — separate pipe, fully overlapped with the FMA stream here.
__device__ __forceinline__ float ex2_fast(float y) {
    float r; asm("ex2.approx.ftz.f32 %0, %1;" : "=f"(r) : "f"(y)); return r;
}

// ---------------- qkv (analytic circuit), coalesced x reads ----------------
// Circuit identity: every RX(p_w) commutes backward to the front (wire w is only
// ever the TARGET of the single CNOT it must cross), giving a product state with
// theta_w = x_w + p_w followed by the classical XOR ladder. Z-expectations:
//   z_0 = prod_{w=1..7} cos(theta_w),  z_v = prod_{w=0..v} cos(theta_w)  (v>=1)
// x is read LINEARLY (fully coalesced); the scattered [B,H,S,8] stores are
// fire-and-forget (store wavefronts don't stall the warp).
__global__ void __launch_bounds__(256) qkv_kernel(const float* __restrict__ x,
                                                  const float* __restrict__ rxp) {
    int idx = blockIdx.x * 256 + threadIdx.x;  // element id in [0, 65536)
    const float4* xv = (const float4*)(x) + idx * 2;
    float4 x0 = xv[0], x1 = xv[1];

    float t0 = __cosf(x0.x + rxp[0]);
    float t1 = __cosf(x0.y + rxp[1]);
    float t2 = __cosf(x0.z + rxp[2]);
    float t3 = __cosf(x0.w + rxp[3]);
    float t4 = __cosf(x1.x + rxp[4]);
    float t5 = __cosf(x1.y + rxp[5]);
    float t6 = __cosf(x1.z + rxp[6]);
    float t7 = __cosf(x1.w + rxp[7]);

    t1 *= GAMMA;  // every output contains t1 -> folds the attention pre-scale in

    float z1 = t0 * t1;
    float z2 = z1 * t2;
    float z3 = z2 * t3;
    float z4 = z3 * t4;
    float z5 = z4 * t5;
    float z6 = z5 * t6;
    float z7 = z6 * t7;
    float z0 = t1 * t2;
    z0 *= t3; z0 *= t4; z0 *= t5; z0 *= t6; z0 *= t7;

    int b = idx >> 14;
    int s = (idx >> 4) & 1023;
    int h = idx & 15;
    float4* o = (float4*)(g_qkv + ((((b * 16 + h) * 1024) + s) << 3));
    o[0] = make_float4(z0, z1, z2, z3);
    o[1] = make_float4(z4, z5, z6, z7);
}

// ---------------- attention ----------------
// Grid (16, 64): 64-query tiles x bh = 1024 blocks (6.92/SM, ~1% tail).
// 128 threads (4 warps -> all 4 SMSPs). Split-KV: 2 threads per query;
// threads 0..63 do keys [0,512), threads 64..127 do keys [512,1024);
// partials merged through smem. Scores bounded (|s|<=2.83) -> no max tracking.
// Prologue is a LINEAR coalesced copy of the precomputed qkv tile.
__global__ void __launch_bounds__(128, 7) attn_kernel() {
    __shared__ __align__(16) float kv[1024 * 8];  // 32KB: full K(=V=Q) tile for this bh
    int tid = threadIdx.x;
    int bh = blockIdx.y;
    int b = bh >> 4, h = bh & 15;

    // ---- prologue: coalesced copy (16 blocks/bh read the same 32KB from L2) ----
    const float4* src = (const float4*)(g_qkv + (bh << 13));
    float4* dst = (float4*)kv;
#pragma unroll
    for (int i = 0; i < 16; i++) dst[tid + 128 * i] = src[tid + 128 * i];
    __syncthreads();

    // ---- mainloop: 2 threads per query, 512 keys each, 2 keys per iteration ----
    int qi = tid & 63;                    // query within tile
    int r = blockIdx.x * 64 + qi;         // query row
    int kbase = (tid >> 6) << 9;          // 0 or 512
    const ulonglong2* kvp = (const ulonglong2*)kv;
    ulonglong2 qa = kvp[2 * r], qb = kvp[2 * r + 1];
    u64 q01 = qa.x, q23 = qa.y, q45 = qb.x, q67 = qb.y;

    u64 a01 = 0ull, a23 = 0ull, a45 = 0ull, a67 = 0ull;
    u64 den2 = 0ull;  // packed (den_even, den_odd)

#pragma unroll 2
    for (int jj = 0; jj < 512; jj += 2) {
        int j = kbase + jj;
        ulonglong2 ka0 = kvp[2 * j];      // broadcast LDS.128 (half-warp same addr)
        ulonglong2 kb0 = kvp[2 * j + 1];
        ulonglong2 ka1 = kvp[2 * j + 2];
        ulonglong2 kb1 = kvp[2 * j + 3];

        // packed dots for key j (t0) and key j+1 (t1), sharing q registers
        u64 t0 = f2mul(q01, ka0.x);
        u64 t1 = f2mul(q01, ka1.x);
        t0 = f2fma(q23, ka0.y, t0);
        t1 = f2fma(q23, ka1.y, t1);
        t0 = f2fma(q45, kb0.x, t0);
        t1 = f2fma(q45, kb1.x, t1);
        t0 = f2fma(q67, kb0.y, t0);
        t1 = f2fma(q67, kb1.y, t1);

        // transpose-pack: one f2add performs both horizontal adds -> y = (s0, s1)
        float d0l, d0h, d1l, d1h;
        f2unpack(t0, d0l, d0h);
        f2unpack(t1, d1l, d1h);
        u64 y = f2add(f2pack(d0l, d1l), f2pack(d0h, d1h));

        // MUFU exp2 (y = score * log2(e) via GAMMA prescale, |y| <= ~4.2)
        float y0, y1;
        f2unpack(y, y0, y1);
        float e0 = ex2_fast(y0);
        float e1 = ex2_fast(y1);

        den2 = f2add(den2, f2pack(e0, e1));  // one add updates both denominators
        u64 ee0 = f2bcast(e0);
        u64 ee1 = f2bcast(e1);
        a01 = f2fma(ee0, ka0.x, a01);
        a23 = f2fma(ee0, ka0.y, a23);
        a45 = f2fma(ee0, kb0.x, a45);
        a67 = f2fma(ee0, kb0.y, a67);
        a01 = f2fma(ee1, ka1.x, a01);
        a23 = f2fma(ee1, ka1.y, a23);
        a45 = f2fma(ee1, kb1.x, a45);
        a67 = f2fma(ee1, kb1.y, a67);
    }

    float dl, dh;
    f2unpack(den2, dl, dh);
    float den = dl + dh;

    float o0, o1, o2, o3, o4, o5, o6, o7;
    f2unpack(a01, o0, o1);
    f2unpack(a23, o2, o3);
    f2unpack(a45, o4, o5);
    f2unpack(a67, o6, o7);

    // ---- merge the two key-halves (kv reused as scratch; stride 9 is coprime
    //      with 32 banks -> conflict-free scalar access) ----
    __syncthreads();  // all kv reads complete before overwrite
    if (tid >= 64) {
        float* sc = kv + (tid - 64) * 9;
        sc[0] = den;
        sc[1] = o0; sc[2] = o1; sc[3] = o2; sc[4] = o3;
        sc[5] = o4; sc[6] = o5; sc[7] = o6; sc[8] = o7;
    }
    __syncthreads();
    if (tid < 64) {
        const float* sc = kv + tid * 9;
        den += sc[0];
        o0 += sc[1]; o1 += sc[2]; o2 += sc[3]; o3 += sc[4];
        o4 += sc[5]; o5 += sc[6]; o6 += sc[7]; o7 += sc[8];

        float inv = __fdividef(INV_GAMMA, den);  // undo GAMMA scaling of V
        float4* out4 = (float4*)g_attn + ((((b << 10) + r) * 16 + h) << 1);
        out4[0] = make_float4(o0 * inv, o1 * inv, o2 * inv, o3 * inv);
        out4[1] = make_float4(o4 * inv, o5 * inv, o6 * inv, o7 * inv);
    }
}

// ---------------- W transpose (so combine reads coalesced) ----------------
__global__ void __launch_bounds__(256) wt_kernel(const float* __restrict__ w) {
    int idx = blockIdx.x * 256 + threadIdx.x;  // 16384
    int j = idx >> 7, e = idx & 127;
    g_wt[e * 128 + j] = w[idx];
}

// ---------------- combine: out[4096,128] = attn[4096,128] @ W^T ----------------
// ncu R11: old shape (128 blocks) ran at occ=12.1%, issue=12.6% -> latency-bound,
// 29.9us. New shape: 1024 blocks x 128 threads (6.92 blocks/SM, ~28 warps/SM),
// 4 rows/block, 4 independent accumulators per wv load.
__global__ void __launch_bounds__(128) combine_kernel(float* __restrict__ out) {
    __shared__ __align__(16) float sA[4 * 128];  // 2KB A tile (4 rows)
    const float* A = g_attn + blockIdx.x * 512;
    int tid = threadIdx.x;
    ((float4*)sA)[tid] = ((const float4*)A)[tid];  // 128 x 16B = 2KB, coalesced
    __syncthreads();

    float a0 = 0.f, a1 = 0.f, a2 = 0.f, a3 = 0.f;
#pragma unroll 8
    for (int e = 0; e < 128; e++) {
        float wv = __ldg(&g_wt[e * 128 + tid]);  // coalesced; L1-resident
        a0 = fmaf(sA[e], wv, a0);                // broadcast LDS, 4-way ILP
        a1 = fmaf(sA[128 + e], wv, a1);
        a2 = fmaf(sA[256 + e], wv, a2);
        a3 = fmaf(sA[384 + e], wv, a3);
    }

    int row = blockIdx.x * 4;
    out[row * 128 + tid] = a0;           // coalesced stores
    out[(row + 1) * 128 + tid] = a1;
    out[(row + 2) * 128 + tid] = a2;
    out[(row + 3) * 128 + tid] = a3;
}

// ---------------- launch ----------------
// Order chosen so ncu (-s 5 -c 1, correctness pass = launches 1-4) captures
// launch #6 = attn_kernel next profile. Dependencies: qkv<attn, wt<combine.
extern "C" void kernel_launch(void* const* d_in, const int* in_sizes, int n_in,
                              void* d_out, int out_size) {
    const float* x   = (const float*)d_in[0];  // [4,1024,128]
    const float* rxp = (const float*)d_in[1];  // [8]
    const float* w   = (const float*)d_in[2];  // [128,128]
    float* out = (float*)d_out;                // [4,1024,128]

    qkv_kernel<<<256, 256>>>(x, rxp);          // coalesced x reads
    attn_kernel<<<dim3(16, 64), 128>>>();      // (64-query tile, b*h), 1024 blocks
    wt_kernel<<<64, 256>>>(w);                 // independent; placed for ncu phasing
    combine_kernel<<<1024, 128>>>(out);        // occupancy-fixed GEMM
}

// round 16
// speedup vs baseline: 1.5157x; 1.5157x over previous
#include <cuda_runtime.h>

// ---------------- scratch (no allocations allowed) ----------------
__device__ __align__(16) float g_attn[4 * 1024 * 16 * 8];  // [B,S,H,8]  2MB
__device__ __align__(16) float g_wt[128 * 128];            // W transposed [e][j]

// GAMMA^2 = log2(e)/sqrt(8); dot of GAMMA-scaled vectors = score*log2(e) directly.
#define GAMMA     0.7142163217f
#define INV_GAMMA 1.4001353259f

// ---------------- f32x2 packed helpers (Blackwell dual-FMA pipe) ----------------
typedef unsigned long long u64;

__device__ __forceinline__ u64 f2mul(u64 a, u64 b) {
    u64 d; asm("mul.rn.f32x2 %0, %1, %2;" : "=l"(d) : "l"(a), "l"(b)); return d;
}
__device__ __forceinline__ u64 f2add(u64 a, u64 b) {
    u64 d; asm("add.rn.f32x2 %0, %1, %2;" : "=l"(d) : "l"(a), "l"(b)); return d;
}
__device__ __forceinline__ u64 f2fma(u64 a, u64 b, u64 c) {
    u64 d; asm("fma.rn.f32x2 %0, %1, %2, %3;" : "=l"(d) : "l"(a), "l"(b), "l"(c)); return d;
}
__device__ __forceinline__ u64 f2pack(float lo, float hi) {
    u64 d; asm("mov.b64 %0, {%1, %2};" : "=l"(d) : "f"(lo), "f"(hi)); return d;
}
__device__ __forceinline__ void f2unpack(u64 v, float& lo, float& hi) {
    asm("mov.b64 {%0, %1}, %2;" : "=f"(lo), "=f"(hi) : "l"(v));
}
__device__ __forceinline__ u64 f2bcast(float x) { return f2pack(x, x); }

// MUFU exp2 — separate pipe, fully overlapped with the FMA stream here.
__device__ __forceinline__ float ex2_fast(float y) {
    float r; asm("ex2.approx.ftz.f32 %0, %1;" : "=f"(r) : "f"(y)); return r;
}

// ---------------- attention — MEASURED BEST (R11: 54.2us incl. prologue) ----------------
// Byte-identical to the 84.1us run's attn. Circuit identity: every RX(p_w)
// commutes to the front (w is only ever a CNOT TARGET), giving theta_w = x_w+p_w
// product state + classical XOR ladder:
//   z_0 = prod_{w=1..7} cos(theta_w),  z_v = prod_{w=0..v} cos(theta_w)  (v>=1)
// Grid (17,64): x<16 = 64-query tiles (1024 blocks); x==16 = W-transpose lane.
// 128 threads; split-KV (2 threads/query, 512 keys each), merge via smem.
__global__ void __launch_bounds__(128, 7) attn_kernel(const float* __restrict__ x,
                                                      const float* __restrict__ rxp,
                                                      const float* __restrict__ w) {
    __shared__ __align__(16) float kv[1024 * 8];  // 32KB: full K(=V=Q) tile for this bh
    int tid = threadIdx.x;

    if (blockIdx.x == 16) {  // W-transpose lane: 64 blocks x 128 threads x 2 elems
        int base = blockIdx.y * 256 + tid;
#pragma unroll
        for (int i = 0; i < 2; i++) {
            int idx = base + 128 * i;       // coalesced read of w
            int j = idx >> 7, e = idx & 127;
            g_wt[e * 128 + j] = w[idx];
        }
        return;  // uniform for the whole block: no barrier divergence
    }

    int bh = blockIdx.y;
    int b = bh >> 4, h = bh & 15;

    float p0 = rxp[0], p1 = rxp[1], p2 = rxp[2], p3 = rxp[3];
    float p4 = rxp[4], p5 = rxp[5], p6 = rxp[6], p7 = rxp[7];

    // ---- prologue: build the GAMMA-scaled qkv tile for this (b,h) in smem ----
#pragma unroll
    for (int i = 0; i < 8; i++) {
        int s = tid + 128 * i;
        const float4* xr = (const float4*)(x + ((((b << 10) + s) * 16 + h) << 3));
        float4 x0 = xr[0], x1 = xr[1];

        float t0 = __cosf(x0.x + p0);
        float t1 = __cosf(x0.y + p1);
        float t2 = __cosf(x0.z + p2);
        float t3 = __cosf(x0.w + p3);
        float t4 = __cosf(x1.x + p4);
        float t5 = __cosf(x1.y + p5);
        float t6 = __cosf(x1.z + p6);
        float t7 = __cosf(x1.w + p7);

        t1 *= GAMMA;  // every output contains t1 -> folds the attention pre-scale in

        float z1 = t0 * t1;
        float z2 = z1 * t2;
        float z3 = z2 * t3;
        float z4 = z3 * t4;
        float z5 = z4 * t5;
        float z6 = z5 * t6;
        float z7 = z6 * t7;
        float z0 = t1 * t2;
        z0 *= t3; z0 *= t4; z0 *= t5; z0 *= t6; z0 *= t7;

        float4* o = (float4*)(kv + (s << 3));
        o[0] = make_float4(z0, z1, z2, z3);
        o[1] = make_float4(z4, z5, z6, z7);
    }
    __syncthreads();

    // ---- mainloop: 2 threads per query, 512 keys each, 2 keys per iteration ----
    int qi = tid & 63;                    // query within tile
    int r = blockIdx.x * 64 + qi;         // query row
    int kbase = (tid >> 6) << 9;          // 0 or 512
    const ulonglong2* kvp = (const ulonglong2*)kv;
    ulonglong2 qa = kvp[2 * r], qb = kvp[2 * r + 1];
    u64 q01 = qa.x, q23 = qa.y, q45 = qb.x, q67 = qb.y;

    u64 a01 = 0ull, a23 = 0ull, a45 = 0ull, a67 = 0ull;
    u64 den2 = 0ull;  // packed (den_even, den_odd)

#pragma unroll 2
    for (int jj = 0; jj < 512; jj += 2) {
        int j = kbase + jj;
        ulonglong2 ka0 = kvp[2 * j];      // broadcast LDS.128 (half-warp same addr)
        ulonglong2 kb0 = kvp[2 * j + 1];
        ulonglong2 ka1 = kvp[2 * j + 2];
        ulonglong2 kb1 = kvp[2 * j + 3];

        // packed dots for key j (t0) and key j+1 (t1), sharing q registers
        u64 t0 = f2mul(q01, ka0.x);
        u64 t1 = f2mul(q01, ka1.x);
        t0 = f2fma(q23, ka0.y, t0);
        t1 = f2fma(q23, ka1.y, t1);
        t0 = f2fma(q45, kb0.x, t0);
        t1 = f2fma(q45, kb1.x, t1);
        t0 = f2fma(q67, kb0.y, t0);
        t1 = f2fma(q67, kb1.y, t1);

        // transpose-pack: one f2add performs both horizontal adds -> y = (s0, s1)
        float d0l, d0h, d1l, d1h;
        f2unpack(t0, d0l, d0h);
        f2unpack(t1, d1l, d1h);
        u64 y = f2add(f2pack(d0l, d1l), f2pack(d0h, d1h));

        // MUFU exp2 (y = score * log2(e) via GAMMA prescale, |y| <= ~4.2)
        float y0, y1;
        f2unpack(y, y0, y1);
        float e0 = ex2_fast(y0);
        float e1 = ex2_fast(y1);

        den2 = f2add(den2, f2pack(e0, e1));  // one add updates both denominators
        u64 ee0 = f2bcast(e0);
        u64 ee1 = f2bcast(e1);
        a01 = f2fma(ee0, ka0.x, a01);
        a23 = f2fma(ee0, ka0.y, a23);
        a45 = f2fma(ee0, kb0.x, a45);
        a67 = f2fma(ee0, kb0.y, a67);
        a01 = f2fma(ee1, ka1.x, a01);
        a23 = f2fma(ee1, ka1.y, a23);
        a45 = f2fma(ee1, kb1.x, a45);
        a67 = f2fma(ee1, kb1.y, a67);
    }

    float dl, dh;
    f2unpack(den2, dl, dh);
    float den = dl + dh;

    float o0, o1, o2, o3, o4, o5, o6, o7;
    f2unpack(a01, o0, o1);
    f2unpack(a23, o2, o3);
    f2unpack(a45, o4, o5);
    f2unpack(a67, o6, o7);

    // ---- merge the two key-halves (kv reused as scratch; stride 9 conflict-free) ----
    __syncthreads();  // all kv reads complete before overwrite
    if (tid >= 64) {
        float* sc = kv + (tid - 64) * 9;
        sc[0] = den;
        sc[1] = o0; sc[2] = o1; sc[3] = o2; sc[4] = o3;
        sc[5] = o4; sc[6] = o5; sc[7] = o6; sc[8] = o7;
    }
    __syncthreads();
    if (tid < 64) {
        const float* sc = kv + tid * 9;
        den += sc[0];
        o0 += sc[1]; o1 += sc[2]; o2 += sc[3]; o3 += sc[4];
        o4 += sc[5]; o5 += sc[6]; o6 += sc[7]; o7 += sc[8];

        float inv = __fdividef(INV_GAMMA, den);  // undo GAMMA scaling of V
        float4* out4 = (float4*)g_attn + ((((b << 10) + r) * 16 + h) << 1);
        out4[0] = make_float4(o0 * inv, o1 * inv, o2 * inv, o3 * inv);
        out4[1] = make_float4(o4 * inv, o5 * inv, o6 * inv, o7 * inv);
    }
}

// ---------------- combine: out[4096,128] = attn[4096,128] @ W^T ----------------
// ncu R13 (1024x128, 4 scalar LDS/iter): 21.4us, L1=39.7% wf-bound, occ=41%.
// Fix: A-tile stored TRANSPOSED in smem (sAT[e*4+r]) so ONE broadcast LDS.128
// per e fetches all 4 row values -> 2 wavefronts/iter/warp instead of 5.
// Model: ~7K wf/SM ≈ 4us; FMA side ~4us -> ~5-7us expected.
__global__ void __launch_bounds__(128) combine_kernel(float* __restrict__ out) {
    __shared__ __align__(16) float sAT[128 * 4];  // transposed 4-row tile: [e][r]
    const float* A = g_attn + blockIdx.x * 512;   // 4 rows x 128
    int tid = threadIdx.x;
#pragma unroll
    for (int r = 0; r < 4; r++)
        sAT[tid * 4 + r] = A[r * 128 + tid];      // coalesced reads; one-time store
    __syncthreads();

    float a0 = 0.f, a1 = 0.f, a2 = 0.f, a3 = 0.f;
#pragma unroll 8
    for (int e = 0; e < 128; e++) {
        float wv = __ldg(&g_wt[e * 128 + tid]);   // coalesced, 1 wf (128B line)
        float4 av = *(const float4*)&sAT[e * 4];  // broadcast LDS.128, 1 wf
        a0 = fmaf(av.x, wv, a0);
        a1 = fmaf(av.y, wv, a1);
        a2 = fmaf(av.z, wv, a2);
        a3 = fmaf(av.w, wv, a3);
    }

    int row = blockIdx.x * 4;
    out[row * 128 + tid] = a0;                    // coalesced stores
    out[(row + 1) * 128 + tid] = a1;
    out[(row + 2) * 128 + tid] = a2;
    out[(row + 3) * 128 + tid] = a3;
}

// ---------------- launch ----------------
extern "C" void kernel_launch(void* const* d_in, const int* in_sizes, int n_in,
                              void* d_out, int out_size) {
    const float* x   = (const float*)d_in[0];  // [4,1024,128]
    const float* rxp = (const float*)d_in[1];  // [8]
    const float* w   = (const float*)d_in[2];  // [128,128]
    float* out = (float*)d_out;                // [4,1024,128]

    attn_kernel<<<dim3(17, 64), 128>>>(x, rxp, w);  // attn tiles + folded W-transpose
    combine_kernel<<<1024, 128>>>(out);             // L1-wavefront-fixed GEMM
}